// round 13
// baseline (speedup 1.0000x reference)
#include <cuda_runtime.h>
#include <cstddef>

// ---- constants ----------------------------------------------------------
constexpr int BATCH = 64;
constexpr int C13 = BATCH * 13 * 13;            // 10816
constexpr int C26 = BATCH * 26 * 26;            // 43264
constexpr int C52 = BATCH * 52 * 52;            // 173056
constexpr int TOT_CELLS = C13 + C26 + C52;      // 227136
constexpr int THREADS = 256;
constexpr int ABLK = (TOT_CELLS + THREADS - 1) / THREADS;   // 888 = 148*6 (!)
constexpr int NB   = 1184;                                   // 148 SMs * 8 blocks: ONE wave

// One FCOS cell -> 25 floats into smem staging (stride-25, conflict-free).
template<int S>
__device__ __forceinline__ void assign_cell(int local,
                                            const float4* __restrict__ bboxes4,
                                            const int*    __restrict__ labels,
                                            float*        __restrict__ st)  // &stage[tid*25]
{
    const int b    = local / (S * S);
    const int cell = local % (S * S);
    const int ii = cell % S;   // x
    const int jj = cell / S;   // y

    const float stride     = 416.0f / (float)S;
    const float inv_stride = (float)S / 416.0f;   // exact (stride = 32/16/8)
    const float fii = (float)ii;
    const float fjj = (float)jj;
    const float cxc = (fii + 0.5f) * stride;
    const float cyc = (fjj + 0.5f) * stride;

    unsigned clsmask = 0u;
    float reg0 = 0.f, reg1 = 0.f, reg2 = 0.f, reg3 = 0.f, reg4 = 0.f;

    const float4* bb = bboxes4 + b * 32;
    const int*    lb = labels  + b * 32;

    #pragma unroll 4
    for (int n = 0; n < 32; ++n) {
        const float4 bx = __ldg(bb + n);
        const float cx = bx.x, cy = bx.y, bw = bx.z, bh = bx.w;

        const float pos0 = floorf(cx * inv_stride);
        const float pos1 = floorf(cy * inv_stride);
        const float bp0  = floorf(0.5f * bw * inv_stride);
        const float bp1  = floorf(0.5f * bh * inv_stride);

        const bool region = (fii >= pos0 - bp0) && (fii < pos0 + bp0) &&
                            (fjj >= pos1 - bp1) && (fjj < pos1 + bp1);

        if (region) clsmask |= (1u << __ldg(lb + n));

        const float hw = floorf(bw * 0.5f);
        const float hh = floorf(bh * 0.5f);
        const float l  = cxc - (cx - hw);
        const float r  = (cx + hw) - cxc;
        const float t  = cyc - (cy - hh);
        const float bo = (cy + hh) - cyc;

        const float mlr = fmaxf(l, r);
        const float mtb = fmaxf(t, bo);
        const float m   = fmaxf(mlr, mtb);

        bool band;
        if (S == 13)      band = (m > 256.0f);
        else if (S == 26) band = (m > 64.0f) && (m <= 256.0f);
        else              band = (m <= 64.0f);

        if (region && band) {
            const float regmax = fmaxf(fmaxf(fmaxf(reg0, reg1), fmaxf(reg2, reg3)), reg4);
            if (regmax == 0.0f || m < regmax) {
                const float cent = sqrtf(fminf(l, r) * fminf(t, bo) / (mlr * mtb));
                reg0 = fmaxf(l  * inv_stride, 0.0f);
                reg1 = fmaxf(t  * inv_stride, 0.0f);
                reg2 = fmaxf(r  * inv_stride, 0.0f);
                reg3 = fmaxf(bo * inv_stride, 0.0f);
                reg4 = fmaxf(cent, 0.0f);
            }
        }
    }

    #pragma unroll
    for (int c = 0; c < 20; ++c)
        st[c] = ((clsmask >> c) & 1u) ? 1.0f : 0.0f;
    st[20] = reg0; st[21] = reg1; st[22] = reg2; st[23] = reg3; st[24] = reg4;
}

__global__ __launch_bounds__(THREADS, 8)
void fused_kernel(const float4* __restrict__ img4,
                  float4*       __restrict__ out4,
                  int n4,
                  const float4* __restrict__ bboxes4,
                  const int*    __restrict__ labels,
                  float*        __restrict__ out_t)   // contiguous target region (cell*25)
{
    __shared__ float stage[THREADS * 25];   // 25.6 KB (fits 8 blocks/SM: 204.8 < 228 KB)

    const int bid = blockIdx.x;
    const int tid = threadIdx.x;

    // ---- Phase 1: FCOS assignment on blocks 0..887 (6 per SM, round-robin) ----
    if (bid < ABLK) {
        const int g = bid * THREADS + tid;
        if (g < C13)              assign_cell<13>(g,             bboxes4, labels, &stage[tid * 25]);
        else if (g < C13 + C26)   assign_cell<26>(g - C13,       bboxes4, labels, &stage[tid * 25]);
        else if (g < TOT_CELLS)   assign_cell<52>(g - C13 - C26, bboxes4, labels, &stage[tid * 25]);
        __syncthreads();

        const int ncells = min(THREADS, TOT_CELLS - bid * THREADS);
        const int nf4 = (ncells * 25) / 4;                     // 1600 or 400 (both exact)
        float4* dst = reinterpret_cast<float4*>(out_t + (size_t)bid * THREADS * 25);
        const float4* src = reinterpret_cast<const float4*>(stage);
        for (int k = tid; k < nf4; k += THREADS)
            dst[k] = src[k];
    }

    // ---- Phase 2: image copy shared by ALL blocks, grid-stride, MLP-4 ----
    const int stride = NB * THREADS;          // 303104
    int i = bid * THREADS + tid;
    for (; i + 3 * stride < n4; i += 4 * stride) {
        float4 a = __ldcs(img4 + i);
        float4 b = __ldcs(img4 + i + stride);
        float4 c = __ldcs(img4 + i + 2 * stride);
        float4 d = __ldcs(img4 + i + 3 * stride);
        __stcs(out4 + i,              a);
        __stcs(out4 + i + stride,     b);
        __stcs(out4 + i + 2 * stride, c);
        __stcs(out4 + i + 3 * stride, d);
    }
    for (; i < n4; i += stride)
        __stcs(out4 + i, __ldcs(img4 + i));
}

extern "C" void kernel_launch(void* const* d_in, const int* in_sizes, int n_in,
                              void* d_out, int out_size)
{
    const float* image  = (const float*)d_in[0];
    const float* bboxes = (const float*)d_in[1];
    const int*   labels = (const int*)  d_in[2];
    float* out = (float*)d_out;

    const size_t n_img = (size_t)in_sizes[0];   // 33,226,752 (div by 4; *4B div by 16)
    const int n4 = (int)(n_img / 4);

    float* out_t = out + n_img;   // o13 | o26 | o52 contiguous: flat cell*25 array

    fused_kernel<<<NB, THREADS>>>((const float4*)image, (float4*)out, n4,
                                  (const float4*)bboxes, labels, out_t);
}

// round 14
// speedup vs baseline: 1.0172x; 1.0172x over previous
#include <cuda_runtime.h>
#include <cstddef>

// ---- constants ----------------------------------------------------------
constexpr int BATCH = 64;
constexpr int C13 = BATCH * 13 * 13;            // 10816
constexpr int C26 = BATCH * 26 * 26;            // 43264
constexpr int C52 = BATCH * 52 * 52;            // 173056
constexpr int TOT_CELLS = C13 + C26 + C52;      // 227136
constexpr int THREADS = 256;
constexpr int ABLK = 888;                        // assign blocks (888*256 >= TOT_CELLS)
constexpr int CBLK = 1480;                       // copy-only blocks
constexpr int NB   = ABLK + CBLK;                // 2368

// Copy partition: units of 256 float4. Total units U = n4/256 = 32448.
//   assign blocks: QA=8 units each            -> 7104
//   copy blocks:   first 184 take 18, rest 17 -> 3312 + 22032
//   7104 + 3312 + 22032 = 32448 (exact)
constexpr int QA = 8;
constexpr int QC = 17;
constexpr int EXTRA = 184;                       // first EXTRA copy blocks take QC+1

// One FCOS cell -> 25 floats into smem staging (stride-25, conflict-free).
template<int S>
__device__ __forceinline__ void assign_cell(int local,
                                            const float4* __restrict__ bboxes4,
                                            const int*    __restrict__ labels,
                                            float*        __restrict__ st)  // &stage[tid*25]
{
    const int b    = local / (S * S);
    const int cell = local % (S * S);
    const int ii = cell % S;   // x
    const int jj = cell / S;   // y

    const float stride     = 416.0f / (float)S;
    const float inv_stride = (float)S / 416.0f;   // exact (stride = 32/16/8)
    const float fii = (float)ii;
    const float fjj = (float)jj;
    const float cxc = (fii + 0.5f) * stride;
    const float cyc = (fjj + 0.5f) * stride;

    unsigned clsmask = 0u;
    float reg0 = 0.f, reg1 = 0.f, reg2 = 0.f, reg3 = 0.f, reg4 = 0.f;

    const float4* bb = bboxes4 + b * 32;
    const int*    lb = labels  + b * 32;

    #pragma unroll 4
    for (int n = 0; n < 32; ++n) {
        const float4 bx = __ldg(bb + n);
        const float cx = bx.x, cy = bx.y, bw = bx.z, bh = bx.w;

        const float pos0 = floorf(cx * inv_stride);
        const float pos1 = floorf(cy * inv_stride);
        const float bp0  = floorf(0.5f * bw * inv_stride);
        const float bp1  = floorf(0.5f * bh * inv_stride);

        const bool region = (fii >= pos0 - bp0) && (fii < pos0 + bp0) &&
                            (fjj >= pos1 - bp1) && (fjj < pos1 + bp1);

        if (region) clsmask |= (1u << __ldg(lb + n));

        const float hw = floorf(bw * 0.5f);
        const float hh = floorf(bh * 0.5f);
        const float l  = cxc - (cx - hw);
        const float r  = (cx + hw) - cxc;
        const float t  = cyc - (cy - hh);
        const float bo = (cy + hh) - cyc;

        const float mlr = fmaxf(l, r);
        const float mtb = fmaxf(t, bo);
        const float m   = fmaxf(mlr, mtb);

        bool band;
        if (S == 13)      band = (m > 256.0f);
        else if (S == 26) band = (m > 64.0f) && (m <= 256.0f);
        else              band = (m <= 64.0f);

        if (region && band) {
            const float regmax = fmaxf(fmaxf(fmaxf(reg0, reg1), fmaxf(reg2, reg3)), reg4);
            if (regmax == 0.0f || m < regmax) {
                const float cent = sqrtf(fminf(l, r) * fminf(t, bo) / (mlr * mtb));
                reg0 = fmaxf(l  * inv_stride, 0.0f);
                reg1 = fmaxf(t  * inv_stride, 0.0f);
                reg2 = fmaxf(r  * inv_stride, 0.0f);
                reg3 = fmaxf(bo * inv_stride, 0.0f);
                reg4 = fmaxf(cent, 0.0f);
            }
        }
    }

    #pragma unroll
    for (int c = 0; c < 20; ++c)
        st[c] = ((clsmask >> c) & 1u) ? 1.0f : 0.0f;
    st[20] = reg0; st[21] = reg1; st[22] = reg2; st[23] = reg3; st[24] = reg4;
}

// Copy q units (each unit = 256 float4) starting at unit u0. Coalesced, MLP-4.
__device__ __forceinline__ void copy_chunk(const float4* __restrict__ img4,
                                           float4*       __restrict__ out4,
                                           int u0, int q, int tid)
{
    const float4* src = img4 + (size_t)u0 * 256 + tid;
    float4*       dst = out4 + (size_t)u0 * 256 + tid;
    int k = 0;
    for (; k + 4 <= q; k += 4) {
        float4 a = __ldcs(src + (size_t)(k    ) * 256);
        float4 b = __ldcs(src + (size_t)(k + 1) * 256);
        float4 c = __ldcs(src + (size_t)(k + 2) * 256);
        float4 d = __ldcs(src + (size_t)(k + 3) * 256);
        __stcs(dst + (size_t)(k    ) * 256, a);
        __stcs(dst + (size_t)(k + 1) * 256, b);
        __stcs(dst + (size_t)(k + 2) * 256, c);
        __stcs(dst + (size_t)(k + 3) * 256, d);
    }
    for (; k < q; ++k)
        __stcs(dst + (size_t)k * 256, __ldcs(src + (size_t)k * 256));
}

__global__ __launch_bounds__(THREADS, 8)
void fused_kernel(const float4* __restrict__ img4,
                  float4*       __restrict__ out4,
                  const float4* __restrict__ bboxes4,
                  const int*    __restrict__ labels,
                  float*        __restrict__ out_t)   // contiguous target region (cell*25)
{
    __shared__ float stage[THREADS * 25];   // 25.6 KB

    const int bid = blockIdx.x;
    const int tid = threadIdx.x;

    if (bid < ABLK) {
        // ---- Assign blocks: FCOS targets + small copy chunk ----
        const int g = bid * THREADS + tid;
        if (g < C13)              assign_cell<13>(g,             bboxes4, labels, &stage[tid * 25]);
        else if (g < C13 + C26)   assign_cell<26>(g - C13,       bboxes4, labels, &stage[tid * 25]);
        else if (g < TOT_CELLS)   assign_cell<52>(g - C13 - C26, bboxes4, labels, &stage[tid * 25]);
        __syncthreads();

        const int ncells = min(THREADS, TOT_CELLS - bid * THREADS);
        const int nf4 = (ncells * 25) / 4;                     // 1600 or 400 (both exact)
        float4* dst = reinterpret_cast<float4*>(out_t + (size_t)bid * THREADS * 25);
        const float4* src = reinterpret_cast<const float4*>(stage);
        for (int k = tid; k < nf4; k += THREADS)
            dst[k] = src[k];

        // small copy share: QA units
        copy_chunk(img4, out4, bid * QA, QA, tid);
    } else {
        // ---- Copy-only blocks: larger share ----
        const int cb = bid - ABLK;                             // 0..CBLK-1
        const int q  = QC + (cb < EXTRA ? 1 : 0);
        const int u0 = ABLK * QA + cb * QC + min(cb, EXTRA);
        copy_chunk(img4, out4, u0, q, tid);
    }
}

extern "C" void kernel_launch(void* const* d_in, const int* in_sizes, int n_in,
                              void* d_out, int out_size)
{
    const float* image  = (const float*)d_in[0];
    const float* bboxes = (const float*)d_in[1];
    const int*   labels = (const int*)  d_in[2];
    float* out = (float*)d_out;

    const size_t n_img = (size_t)in_sizes[0];   // 33,226,752 floats

    float* out_t = out + n_img;   // o13 | o26 | o52 contiguous: flat cell*25 array

    fused_kernel<<<NB, THREADS>>>((const float4*)image, (float4*)out,
                                  (const float4*)bboxes, labels, out_t);
}

// round 15
// speedup vs baseline: 1.0454x; 1.0277x over previous
#include <cuda_runtime.h>
#include <cstddef>

// ---- constants ----------------------------------------------------------
constexpr int BATCH = 64;
constexpr int C13 = BATCH * 13 * 13;            // 10816
constexpr int C26 = BATCH * 26 * 26;            // 43264
constexpr int C52 = BATCH * 52 * 52;            // 173056
constexpr int TOT_CELLS = C13 + C26 + C52;      // 227136
constexpr int THREADS = 256;
constexpr int ABLK = 888;                        // assign-only blocks
constexpr int CBLK = 1480;                       // copy-only blocks
constexpr int NB   = ABLK + CBLK;                // 2368 (R12 shape: best known)

// 256-bit streaming copy helpers (sm_100+: LDG.E.256 / STG.E.256).
struct V8 { float f0,f1,f2,f3,f4,f5,f6,f7; };

__device__ __forceinline__ V8 ldcs_v8(const float* p) {
    V8 v;
    asm volatile("ld.global.cs.v8.f32 {%0,%1,%2,%3,%4,%5,%6,%7}, [%8];"
                 : "=f"(v.f0), "=f"(v.f1), "=f"(v.f2), "=f"(v.f3),
                   "=f"(v.f4), "=f"(v.f5), "=f"(v.f6), "=f"(v.f7)
                 : "l"(p));
    return v;
}
__device__ __forceinline__ void stcs_v8(float* p, const V8& v) {
    asm volatile("st.global.cs.v8.f32 [%0], {%1,%2,%3,%4,%5,%6,%7,%8};"
                 :: "l"(p),
                    "f"(v.f0), "f"(v.f1), "f"(v.f2), "f"(v.f3),
                    "f"(v.f4), "f"(v.f5), "f"(v.f6), "f"(v.f7)
                 : "memory");
}

// One FCOS cell -> 25 floats into smem staging (stride-25, conflict-free).
template<int S>
__device__ __forceinline__ void assign_cell(int local,
                                            const float4* __restrict__ bboxes4,
                                            const int*    __restrict__ labels,
                                            float*        __restrict__ st)  // &stage[tid*25]
{
    const int b    = local / (S * S);
    const int cell = local % (S * S);
    const int ii = cell % S;   // x
    const int jj = cell / S;   // y

    const float stride     = 416.0f / (float)S;
    const float inv_stride = (float)S / 416.0f;   // exact (stride = 32/16/8)
    const float fii = (float)ii;
    const float fjj = (float)jj;
    const float cxc = (fii + 0.5f) * stride;
    const float cyc = (fjj + 0.5f) * stride;

    unsigned clsmask = 0u;
    float reg0 = 0.f, reg1 = 0.f, reg2 = 0.f, reg3 = 0.f, reg4 = 0.f;

    const float4* bb = bboxes4 + b * 32;
    const int*    lb = labels  + b * 32;

    #pragma unroll 4
    for (int n = 0; n < 32; ++n) {
        const float4 bx = __ldg(bb + n);
        const float cx = bx.x, cy = bx.y, bw = bx.z, bh = bx.w;

        const float pos0 = floorf(cx * inv_stride);
        const float pos1 = floorf(cy * inv_stride);
        const float bp0  = floorf(0.5f * bw * inv_stride);
        const float bp1  = floorf(0.5f * bh * inv_stride);

        const bool region = (fii >= pos0 - bp0) && (fii < pos0 + bp0) &&
                            (fjj >= pos1 - bp1) && (fjj < pos1 + bp1);

        if (region) clsmask |= (1u << __ldg(lb + n));

        const float hw = floorf(bw * 0.5f);
        const float hh = floorf(bh * 0.5f);
        const float l  = cxc - (cx - hw);
        const float r  = (cx + hw) - cxc;
        const float t  = cyc - (cy - hh);
        const float bo = (cy + hh) - cyc;

        const float mlr = fmaxf(l, r);
        const float mtb = fmaxf(t, bo);
        const float m   = fmaxf(mlr, mtb);

        bool band;
        if (S == 13)      band = (m > 256.0f);
        else if (S == 26) band = (m > 64.0f) && (m <= 256.0f);
        else              band = (m <= 64.0f);

        if (region && band) {
            const float regmax = fmaxf(fmaxf(fmaxf(reg0, reg1), fmaxf(reg2, reg3)), reg4);
            if (regmax == 0.0f || m < regmax) {
                const float cent = sqrtf(fminf(l, r) * fminf(t, bo) / (mlr * mtb));
                reg0 = fmaxf(l  * inv_stride, 0.0f);
                reg1 = fmaxf(t  * inv_stride, 0.0f);
                reg2 = fmaxf(r  * inv_stride, 0.0f);
                reg3 = fmaxf(bo * inv_stride, 0.0f);
                reg4 = fmaxf(cent, 0.0f);
            }
        }
    }

    #pragma unroll
    for (int c = 0; c < 20; ++c)
        st[c] = ((clsmask >> c) & 1u) ? 1.0f : 0.0f;
    st[20] = reg0; st[21] = reg1; st[22] = reg2; st[23] = reg3; st[24] = reg4;
}

__global__ __launch_bounds__(THREADS, 8)
void fused_kernel(const float* __restrict__ img,
                  float*       __restrict__ outimg,
                  int n8,                                   // n_img / 8 (v8 elements)
                  const float4* __restrict__ bboxes4,
                  const int*    __restrict__ labels,
                  float*        __restrict__ out_t)        // contiguous targets (cell*25)
{
    const int bid = blockIdx.x;
    const int tid = threadIdx.x;

    if (bid < ABLK) {
        // ---- Assign-only blocks: FCOS targets, smem-staged, coalesced out ----
        __shared__ float stage[THREADS * 25];   // 25.6 KB

        const int g = bid * THREADS + tid;
        if (g < C13)              assign_cell<13>(g,             bboxes4, labels, &stage[tid * 25]);
        else if (g < C13 + C26)   assign_cell<26>(g - C13,       bboxes4, labels, &stage[tid * 25]);
        else if (g < TOT_CELLS)   assign_cell<52>(g - C13 - C26, bboxes4, labels, &stage[tid * 25]);
        __syncthreads();

        const int ncells = min(THREADS, TOT_CELLS - bid * THREADS);
        const int nf4 = (ncells * 25) / 4;                     // 1600 or 400 (both exact)
        float4* dst = reinterpret_cast<float4*>(out_t + (size_t)bid * THREADS * 25);
        const float4* src = reinterpret_cast<const float4*>(stage);
        for (int k = tid; k < nf4; k += THREADS)
            dst[k] = src[k];
    } else {
        // ---- Copy-only blocks: 256-bit streaming grid-stride, MLP-2 ----
        const int cb = bid - ABLK;                  // 0..CBLK-1
        const int stride = CBLK * THREADS;          // in v8 (32B) elements
        int i = cb * THREADS + tid;
        for (; i + stride < n8; i += 2 * stride) {
            V8 a = ldcs_v8(img + (size_t)i * 8);
            V8 b = ldcs_v8(img + (size_t)(i + stride) * 8);
            stcs_v8(outimg + (size_t)i * 8,            a);
            stcs_v8(outimg + (size_t)(i + stride) * 8, b);
        }
        for (; i < n8; i += stride) {
            V8 a = ldcs_v8(img + (size_t)i * 8);
            stcs_v8(outimg + (size_t)i * 8, a);
        }
    }
}

extern "C" void kernel_launch(void* const* d_in, const int* in_sizes, int n_in,
                              void* d_out, int out_size)
{
    const float* image  = (const float*)d_in[0];
    const float* bboxes = (const float*)d_in[1];
    const int*   labels = (const int*)  d_in[2];
    float* out = (float*)d_out;

    const size_t n_img = (size_t)in_sizes[0];   // 33,226,752 (divisible by 8)
    const int n8 = (int)(n_img / 8);            // 4,153,344 v8 elements

    float* out_t = out + n_img;   // o13 | o26 | o52 contiguous: flat cell*25 array

    fused_kernel<<<NB, THREADS>>>(image, out, n8,
                                  (const float4*)bboxes, labels, out_t);
}